// round 5
// baseline (speedup 1.0000x reference)
#include <cuda_runtime.h>
#include <cstddef>
#include <cstdint>

#define NN 50000
#define EE 800000

// ---------------- scratch ----------------
__device__ float g_buf0[NN * 128];
__device__ float g_buf1[NN * 256];
__device__ float g_buf2[NN * 128];
__device__ int   g_deg[NN];          // edge-only in-degree (memset 0)
__device__ int   g_cursor[NN];       // memset 0
__device__ int   g_rowptr[NN + 1];
__device__ unsigned long long g_desc[256];   // lookback descriptors (memset 0)
__device__ int   g_src[EE];
__device__ float g_w[EE];            // w[p] = dinv[src[p]]
__device__ float g_dinv[NN];

// ---------------- CSR build ----------------
__global__ void hist_k(const int* __restrict__ col, int* deg, int e) {
    int i = blockIdx.x * blockDim.x + threadIdx.x;
    if (i < e) atomicAdd(&deg[col[i]], 1);
}

// fused: dinv + single-pass exclusive scan of deg (edge counts) via decoupled lookback
__global__ void scan_k(const int* __restrict__ deg, float* __restrict__ dinv,
                       int* __restrict__ rowptr, unsigned long long* desc,
                       int n, int total) {
    int b = blockIdx.x;
    int i = b * 256 + threadIdx.x;
    int lane = threadIdx.x & 31, wid = threadIdx.x >> 5;

    int v = (i < n) ? deg[i] : 0;
    if (i < n) dinv[i] = rsqrtf((float)(v + 1));   // +1 for self-loop

    // block-local inclusive scan
    int x = v;
    #pragma unroll
    for (int off = 1; off < 32; off <<= 1) {
        int t = __shfl_up_sync(0xFFFFFFFFu, x, off);
        if (lane >= off) x += t;
    }
    __shared__ int ws[8];
    __shared__ int s_prefix;
    if (lane == 31) ws[wid] = x;
    __syncthreads();
    if (wid == 0 && lane < 8) {
        int w = ws[lane];
        #pragma unroll
        for (int off = 1; off < 8; off <<= 1) {
            int t = __shfl_up_sync(0xFFu, w, off);
            if (lane >= off) w += t;
        }
        ws[lane] = w;
    }
    __syncthreads();
    int agg = ws[7];   // block total

    if (threadIdx.x == 0) {
        if (b == 0) {
            atomicExch(&desc[0], (2ull << 32) | (unsigned)agg);
            s_prefix = 0;
            rowptr[n] = total;
        } else {
            __threadfence();
            atomicExch(&desc[b], (1ull << 32) | (unsigned)agg);
            int prefix = 0;
            int j = b - 1;
            while (true) {
                unsigned long long dj;
                do { dj = atomicAdd(&desc[j], 0ull); } while ((dj >> 32) == 0);
                prefix += (int)(unsigned)dj;
                if ((dj >> 32) == 2) break;
                j--;
            }
            __threadfence();
            atomicExch(&desc[b], (2ull << 32) | (unsigned)(prefix + agg));
            s_prefix = prefix;
        }
    }
    __syncthreads();
    int excl = s_prefix + (wid ? ws[wid - 1] : 0) + (x - v);
    if (i < n) rowptr[i] = excl;
}

__global__ void fill_k(const int* __restrict__ row, const int* __restrict__ col,
                       const int* __restrict__ rowptr, int* cursor,
                       int* src, float* w, const float* __restrict__ dinv, int e) {
    int i = blockIdx.x * blockDim.x + threadIdx.x;
    if (i < e) {
        int r = row[i], c = col[i];
        int p = rowptr[c] + atomicAdd(&cursor[c], 1);
        src[p] = r;
        w[p] = dinv[r];          // only source-side norm; dest-side applied in agg epilogue
    }
}

// ---------------- aggregation: warp per node, edge loop unrolled x4 ----------------
// out[v] = act( dinv[v] * ( dinv[v]*h[v] + sum_e w[e]*h[src[e]] ) + bias )
template <int VEC, bool BIAS, bool RELU>
__global__ void agg_k(const float* __restrict__ h, float* __restrict__ out,
                      const int* __restrict__ rowptr, const int* __restrict__ src,
                      const float* __restrict__ w, const float* __restrict__ dinv,
                      const float* __restrict__ bias, int nNodes) {
    constexpr int F = 32 * VEC;
    int gw = (blockIdx.x * blockDim.x + threadIdx.x) >> 5;
    int lane = threadIdx.x & 31;
    if (gw >= nNodes) return;
    int v = gw;
    int foff = lane * VEC;

    float acc[VEC];
    float dv = dinv[v];

    const float* hp = h + (size_t)v * F + foff;
    if constexpr (VEC == 4) {
        float4 t = *reinterpret_cast<const float4*>(hp);
        acc[0] = dv * t.x; acc[1] = dv * t.y; acc[2] = dv * t.z; acc[3] = dv * t.w;
    } else if constexpr (VEC == 2) {
        float2 t = *reinterpret_cast<const float2*>(hp);
        acc[0] = dv * t.x; acc[1] = dv * t.y;
    } else {
        acc[0] = dv * hp[0];
    }

    int e0 = rowptr[v], e1 = rowptr[v + 1];
    int e = e0;
    for (; e + 4 <= e1; e += 4) {
        int s0 = src[e], s1 = src[e + 1], s2 = src[e + 2], s3 = src[e + 3];
        float w0 = w[e], w1 = w[e + 1], w2 = w[e + 2], w3 = w[e + 3];
        const float* p0 = h + (size_t)s0 * F + foff;
        const float* p1 = h + (size_t)s1 * F + foff;
        const float* p2 = h + (size_t)s2 * F + foff;
        const float* p3 = h + (size_t)s3 * F + foff;
        if constexpr (VEC == 4) {
            float4 t0 = *reinterpret_cast<const float4*>(p0);
            float4 t1 = *reinterpret_cast<const float4*>(p1);
            float4 t2 = *reinterpret_cast<const float4*>(p2);
            float4 t3 = *reinterpret_cast<const float4*>(p3);
            acc[0] += w0 * t0.x; acc[1] += w0 * t0.y; acc[2] += w0 * t0.z; acc[3] += w0 * t0.w;
            acc[0] += w1 * t1.x; acc[1] += w1 * t1.y; acc[2] += w1 * t1.z; acc[3] += w1 * t1.w;
            acc[0] += w2 * t2.x; acc[1] += w2 * t2.y; acc[2] += w2 * t2.z; acc[3] += w2 * t2.w;
            acc[0] += w3 * t3.x; acc[1] += w3 * t3.y; acc[2] += w3 * t3.z; acc[3] += w3 * t3.w;
        } else if constexpr (VEC == 2) {
            float2 t0 = *reinterpret_cast<const float2*>(p0);
            float2 t1 = *reinterpret_cast<const float2*>(p1);
            float2 t2 = *reinterpret_cast<const float2*>(p2);
            float2 t3 = *reinterpret_cast<const float2*>(p3);
            acc[0] += w0 * t0.x; acc[1] += w0 * t0.y;
            acc[0] += w1 * t1.x; acc[1] += w1 * t1.y;
            acc[0] += w2 * t2.x; acc[1] += w2 * t2.y;
            acc[0] += w3 * t3.x; acc[1] += w3 * t3.y;
        } else {
            float t0 = *p0, t1 = *p1, t2 = *p2, t3 = *p3;
            acc[0] += w0 * t0 + w1 * t1 + w2 * t2 + w3 * t3;
        }
    }
    for (; e < e1; e++) {
        int s = src[e];
        float we = w[e];
        const float* sp = h + (size_t)s * F + foff;
        if constexpr (VEC == 4) {
            float4 t = *reinterpret_cast<const float4*>(sp);
            acc[0] += we * t.x; acc[1] += we * t.y; acc[2] += we * t.z; acc[3] += we * t.w;
        } else if constexpr (VEC == 2) {
            float2 t = *reinterpret_cast<const float2*>(sp);
            acc[0] += we * t.x; acc[1] += we * t.y;
        } else {
            acc[0] += we * sp[0];
        }
    }

    #pragma unroll
    for (int i = 0; i < VEC; i++) {
        float r = dv * acc[i];
        if (BIAS) r += bias[foff + i];
        if (RELU) r = fmaxf(r, 0.0f);
        acc[i] = r;
    }

    float* op = out + (size_t)v * F + foff;
    if constexpr (VEC == 4) {
        float4 t; t.x = acc[0]; t.y = acc[1]; t.z = acc[2]; t.w = acc[3];
        *reinterpret_cast<float4*>(op) = t;
    } else if constexpr (VEC == 2) {
        float2 t; t.x = acc[0]; t.y = acc[1];
        *reinterpret_cast<float2*>(op) = t;
    } else {
        op[0] = acc[0];
    }
}

// ---------------- tf32 tensor-core GEMM (256 threads, 8 warps) ----------------
__device__ __forceinline__ uint32_t f2tf32(float f) {
    uint32_t o;
    asm("cvt.rna.tf32.f32 %0, %1;" : "=r"(o) : "f"(f));
    return o;
}

template <int AN, bool BIAS, bool RELU>
__global__ __launch_bounds__(256, 2)
void gemm_tc(const float* __restrict__ A, const float* __restrict__ B,
             const float* __restrict__ bias, float* __restrict__ C,
             int M, int K, int Nc) {
    constexpr int BN = 2 * AN * 8;
    __shared__ uint32_t As[4][4][132][2];        // [kk][c][m][pair]
    __shared__ uint32_t Bs[4][4][2][BN + 4];     // [kk][c][pair][n]

    const int tid = threadIdx.x;
    const int lane = tid & 31, wid = tid >> 5;
    const int g = lane >> 2, tg = lane & 3;
    const int wm = wid & 3, wn = wid >> 2;

    const int bm = blockIdx.y * 128;
    const int bn = blockIdx.x * BN;

    float acc[2][AN][4];
    #pragma unroll
    for (int i = 0; i < 2; i++)
        #pragma unroll
        for (int j = 0; j < AN; j++)
            #pragma unroll
            for (int c = 0; c < 4; c++) acc[i][j][c] = 0.0f;

    const int arow_l = tid >> 1;
    const int khalf = (tid & 1) * 16;
    const int arow = min(bm + arow_l, M - 1);
    const float* Abase = A + (size_t)arow * K + khalf;

    const int bk = tid >> 3;
    const int bn_l = 4 * (tid & 7);

    for (int kt = 0; kt < K; kt += 32) {
        __syncthreads();
        #pragma unroll
        for (int q = 0; q < 4; q++) {
            float4 v = *reinterpret_cast<const float4*>(Abase + kt + q * 4);
            int kabs = khalf + q * 4;
            int kk = kabs >> 3, pr = (kabs >> 2) & 1;
            As[kk][0][arow_l][pr] = f2tf32(v.x);
            As[kk][1][arow_l][pr] = f2tf32(v.y);
            As[kk][2][arow_l][pr] = f2tf32(v.z);
            As[kk][3][arow_l][pr] = f2tf32(v.w);
        }
        {
            int kk = bk >> 3, pr = (bk >> 2) & 1, c4 = bk & 3;
            const float* Brow = B + (size_t)(kt + bk) * Nc + bn;
            uint32_t* dst = &Bs[kk][c4][pr][0];
            constexpr int NI = BN / 32;
            #pragma unroll
            for (int i = 0; i < NI; i++) {
                int n = bn_l + 32 * i;
                float4 v = *reinterpret_cast<const float4*>(Brow + n);
                uint4 o;
                o.x = f2tf32(v.x); o.y = f2tf32(v.y);
                o.z = f2tf32(v.z); o.w = f2tf32(v.w);
                *reinterpret_cast<uint4*>(dst + n) = o;
            }
        }
        __syncthreads();

        #pragma unroll
        for (int kk = 0; kk < 4; kk++) {
            uint32_t a[2][4];
            #pragma unroll
            for (int ma = 0; ma < 2; ma++) {
                int mb = wm * 32 + ma * 16;
                uint2 lo = *reinterpret_cast<const uint2*>(&As[kk][tg][mb + g][0]);
                uint2 hi = *reinterpret_cast<const uint2*>(&As[kk][tg][mb + 8 + g][0]);
                a[ma][0] = lo.x; a[ma][2] = lo.y;
                a[ma][1] = hi.x; a[ma][3] = hi.y;
            }
            uint32_t b[AN][2];
            #pragma unroll
            for (int na = 0; na < AN; na++) {
                int n = wn * AN * 8 + na * 8 + g;
                b[na][0] = Bs[kk][tg][0][n];
                b[na][1] = Bs[kk][tg][1][n];
            }
            #pragma unroll
            for (int ma = 0; ma < 2; ma++)
                #pragma unroll
                for (int na = 0; na < AN; na++) {
                    asm volatile(
                        "mma.sync.aligned.m16n8k8.row.col.f32.tf32.tf32.f32 "
                        "{%0,%1,%2,%3}, {%4,%5,%6,%7}, {%8,%9}, {%0,%1,%2,%3};\n"
                        : "+f"(acc[ma][na][0]), "+f"(acc[ma][na][1]),
                          "+f"(acc[ma][na][2]), "+f"(acc[ma][na][3])
                        : "r"(a[ma][0]), "r"(a[ma][1]), "r"(a[ma][2]), "r"(a[ma][3]),
                          "r"(b[na][0]), "r"(b[na][1]));
                }
        }
    }

    #pragma unroll
    for (int ma = 0; ma < 2; ma++) {
        int m0 = bm + wm * 32 + ma * 16 + g;
        #pragma unroll
        for (int na = 0; na < AN; na++) {
            int n = bn + wn * AN * 8 + na * 8 + 2 * tg;
            float bx = 0.f, by = 0.f;
            if (BIAS) { bx = bias[n]; by = bias[n + 1]; }
            float v0 = acc[ma][na][0] + bx, v1 = acc[ma][na][1] + by;
            float v2 = acc[ma][na][2] + bx, v3 = acc[ma][na][3] + by;
            if (RELU) {
                v0 = fmaxf(v0, 0.f); v1 = fmaxf(v1, 0.f);
                v2 = fmaxf(v2, 0.f); v3 = fmaxf(v3, 0.f);
            }
            if (m0 < M) {
                float2 o; o.x = v0; o.y = v1;
                *reinterpret_cast<float2*>(C + (size_t)m0 * Nc + n) = o;
            }
            if (m0 + 8 < M) {
                float2 o; o.x = v2; o.y = v3;
                *reinterpret_cast<float2*>(C + (size_t)(m0 + 8) * Nc + n) = o;
            }
        }
    }
}

// ---------------- small fp32 GEMM (Nc <= 32) ----------------
template <int BN, int TN, bool BIAS, bool RELU>
__global__ void gemm_k(const float* __restrict__ A, const float* __restrict__ B,
                       const float* __restrict__ bias, float* __restrict__ C,
                       int M, int K, int Nc) {
    constexpr int BM = 64, BK = 16, TM = 4;
    __shared__ float As[BK][BM];
    __shared__ float Bs[BK][BN];

    int tx = threadIdx.x & 15;
    int ty = threadIdx.x >> 4;
    int bm = blockIdx.y * BM;
    int bn = blockIdx.x * BN;

    float acc[TM][TN];
    #pragma unroll
    for (int i = 0; i < TM; i++)
        #pragma unroll
        for (int j = 0; j < TN; j++) acc[i][j] = 0.0f;

    for (int k0 = 0; k0 < K; k0 += BK) {
        #pragma unroll
        for (int i = 0; i < 4; i++) {
            int lin = threadIdx.x + i * 256;
            int m_l = lin >> 4;
            int k_l = lin & 15;
            int m = bm + m_l;
            As[k_l][m_l] = (m < M) ? A[(size_t)m * K + k0 + k_l] : 0.0f;
        }
        constexpr int BITER = (BK * BN) / 256;
        #pragma unroll
        for (int i = 0; i < BITER; i++) {
            int lin = threadIdx.x + i * 256;
            int k_l = lin / BN;
            int n_l = lin % BN;
            Bs[k_l][n_l] = B[(size_t)(k0 + k_l) * Nc + bn + n_l];
        }
        __syncthreads();

        #pragma unroll
        for (int k = 0; k < BK; k++) {
            float a[TM], b[TN];
            #pragma unroll
            for (int i = 0; i < TM; i++) a[i] = As[k][ty * TM + i];
            #pragma unroll
            for (int j = 0; j < TN; j++) b[j] = Bs[k][tx * TN + j];
            #pragma unroll
            for (int i = 0; i < TM; i++)
                #pragma unroll
                for (int j = 0; j < TN; j++) acc[i][j] += a[i] * b[j];
        }
        __syncthreads();
    }

    #pragma unroll
    for (int i = 0; i < TM; i++) {
        int m = bm + ty * TM + i;
        if (m < M) {
            #pragma unroll
            for (int j = 0; j < TN; j++) {
                int n = bn + tx * TN + j;
                float v = acc[i][j];
                if (BIAS) v += bias[n];
                if (RELU) v = fmaxf(v, 0.0f);
                C[(size_t)m * Nc + n] = v;
            }
        }
    }
}

// ---------------- host ----------------
static inline void* sym(const void* s) {
    void* p = nullptr;
    cudaGetSymbolAddress(&p, s);
    return p;
}

extern "C" void kernel_launch(void* const* d_in, const int* in_sizes, int n_in,
                              void* d_out, int out_size) {
    const float* x   = (const float*)d_in[0];
    const int*   ei  = (const int*)d_in[1];
    const float* W1  = (const float*)d_in[2];
    const float* b1  = (const float*)d_in[3];
    const float* W2  = (const float*)d_in[4];
    const float* b2  = (const float*)d_in[5];
    const float* W3  = (const float*)d_in[6];
    const float* b3  = (const float*)d_in[7];
    const float* W4  = (const float*)d_in[8];
    const float* b4  = (const float*)d_in[9];
    const float* Wmu = (const float*)d_in[10];
    const float* bmu = (const float*)d_in[11];
    const float* Wls = (const float*)d_in[12];
    const float* bls = (const float*)d_in[13];

    const int N = NN;
    const int E = in_sizes[1] / 2;
    const int* row = ei;
    const int* col = ei + E;

    float* buf0 = (float*)sym(g_buf0);
    float* buf1 = (float*)sym(g_buf1);
    float* buf2 = (float*)sym(g_buf2);
    int*   deg  = (int*)sym(g_deg);
    int*   cur  = (int*)sym(g_cursor);
    int*   rp   = (int*)sym(g_rowptr);
    unsigned long long* desc = (unsigned long long*)sym(g_desc);
    int*   srcA = (int*)sym(g_src);
    float* wA   = (float*)sym(g_w);
    float* dinv = (float*)sym(g_dinv);

    float* out_mu = (float*)d_out;
    float* out_ls = out_mu + (size_t)N * 16;

    const int NB = (N + 255) / 256;

    // ---- CSR build: memsets + 3 kernels ----
    cudaMemsetAsync(deg, 0, NN * sizeof(int));
    cudaMemsetAsync(cur, 0, NN * sizeof(int));
    cudaMemsetAsync(desc, 0, 256 * sizeof(unsigned long long));
    hist_k<<<(E + 255) / 256, 256>>>(col, deg, E);
    scan_k<<<NB, 256>>>(deg, dinv, rp, desc, N, E);
    fill_k<<<(E + 255) / 256, 256>>>(row, col, rp, cur, srcA, wA, dinv, E);

    const int AGG_BLOCKS = (N + 7) / 8;  // 8 warps/block

    // ---- L1: aggregate-first (F=128), then tf32 GEMM +b1 +relu -> h1 (N x 256) ----
    agg_k<4, false, false><<<AGG_BLOCKS, 256>>>(x, buf0, rp, srcA, wA, dinv, nullptr, N);  // 4th kernel -> profiled
    {
        dim3 g(2, (N + 127) / 128);
        gemm_tc<8, true, true><<<g, 256>>>(buf0, W1, b1, buf1, N, 128, 256);
    }
    // ---- L2: transform-first (256->128), agg +b2 +relu ----
    {
        dim3 g(1, (N + 127) / 128);
        gemm_tc<8, false, false><<<g, 256>>>(buf1, W2, nullptr, buf0, N, 256, 128);
    }
    agg_k<4, true, true><<<AGG_BLOCKS, 256>>>(buf0, buf2, rp, srcA, wA, dinv, b2, N);
    // ---- L3: transform-first (128->64), agg +b3 +relu ----
    {
        dim3 g(1, (N + 127) / 128);
        gemm_tc<4, false, false><<<g, 256>>>(buf2, W3, nullptr, buf0, N, 128, 64);
    }
    agg_k<2, true, true><<<AGG_BLOCKS, 256>>>(buf0, buf1, rp, srcA, wA, dinv, b3, N);
    // ---- L4: transform-first (64->32), agg +b4 +relu (fp32) ----
    {
        dim3 g(1, (N + 63) / 64);
        gemm_k<32, 2, false, false><<<g, 256>>>(buf1, W4, nullptr, buf0, N, 64, 32);
    }
    agg_k<1, true, true><<<AGG_BLOCKS, 256>>>(buf0, buf2, rp, srcA, wA, dinv, b4, N);
    // ---- heads: shared aggregation (F=32), then two small fp32 GEMMs ----
    agg_k<1, false, false><<<AGG_BLOCKS, 256>>>(buf2, buf0, rp, srcA, wA, dinv, nullptr, N);
    {
        dim3 g(1, (N + 63) / 64);
        gemm_k<16, 1, true, false><<<g, 256>>>(buf0, Wmu, bmu, out_mu, N, 32, 16);
        gemm_k<16, 1, true, false><<<g, 256>>>(buf0, Wls, bls, out_ls, N, 32, 16);
    }
}

// round 6
// speedup vs baseline: 1.0324x; 1.0324x over previous
#include <cuda_runtime.h>
#include <cuda_fp16.h>
#include <cstddef>
#include <cstdint>

#define NN 50000
#define EE 800000

// ---------------- scratch ----------------
__device__ float g_buf0[NN * 128];   // also reused as half[NN*32] for h4
__device__ float g_buf1[NN * 256];
__device__ float g_buf2[NN * 128];   // reused as half[NN*256]: x16 / t2 / t3 / t4
__device__ int   g_deg[NN];
__device__ int   g_cursor[NN];
__device__ int   g_rowptr[NN + 1];
__device__ unsigned long long g_desc[256];
__device__ int   g_src[EE];
__device__ float g_w[EE];            // w[p] = dinv[src[p]]
__device__ float g_dinv[NN];

// ---------------- CSR build + x->fp16 conversion (fused) ----------------
__global__ void histconv_k(const int* __restrict__ col, int* deg, int e,
                           const float* __restrict__ x, __half2* __restrict__ x16,
                           int n4) {
    int i = blockIdx.x * blockDim.x + threadIdx.x;
    if (i < e) atomicAdd(&deg[col[i]], 1);
    if (i < n4) {
        float4 v = reinterpret_cast<const float4*>(x)[i];
        x16[2 * i]     = __floats2half2_rn(v.x, v.y);
        x16[2 * i + 1] = __floats2half2_rn(v.z, v.w);
    }
}

// fused: dinv + single-pass exclusive scan of deg via decoupled lookback
__global__ void scan_k(const int* __restrict__ deg, float* __restrict__ dinv,
                       int* __restrict__ rowptr, unsigned long long* desc,
                       int n, int total) {
    int b = blockIdx.x;
    int i = b * 256 + threadIdx.x;
    int lane = threadIdx.x & 31, wid = threadIdx.x >> 5;

    int v = (i < n) ? deg[i] : 0;
    if (i < n) dinv[i] = rsqrtf((float)(v + 1));   // +1 self-loop

    int x = v;
    #pragma unroll
    for (int off = 1; off < 32; off <<= 1) {
        int t = __shfl_up_sync(0xFFFFFFFFu, x, off);
        if (lane >= off) x += t;
    }
    __shared__ int ws[8];
    __shared__ int s_prefix;
    if (lane == 31) ws[wid] = x;
    __syncthreads();
    if (wid == 0 && lane < 8) {
        int w = ws[lane];
        #pragma unroll
        for (int off = 1; off < 8; off <<= 1) {
            int t = __shfl_up_sync(0xFFu, w, off);
            if (lane >= off) w += t;
        }
        ws[lane] = w;
    }
    __syncthreads();
    int agg = ws[7];

    if (threadIdx.x == 0) {
        if (b == 0) {
            atomicExch(&desc[0], (2ull << 32) | (unsigned)agg);
            s_prefix = 0;
            rowptr[n] = total;
        } else {
            __threadfence();
            atomicExch(&desc[b], (1ull << 32) | (unsigned)agg);
            int prefix = 0;
            int j = b - 1;
            while (true) {
                unsigned long long dj;
                do { dj = atomicAdd(&desc[j], 0ull); } while ((dj >> 32) == 0);
                prefix += (int)(unsigned)dj;
                if ((dj >> 32) == 2) break;
                j--;
            }
            __threadfence();
            atomicExch(&desc[b], (2ull << 32) | (unsigned)(prefix + agg));
            s_prefix = prefix;
        }
    }
    __syncthreads();
    int excl = s_prefix + (wid ? ws[wid - 1] : 0) + (x - v);
    if (i < n) rowptr[i] = excl;
}

__global__ void fill_k(const int* __restrict__ row, const int* __restrict__ col,
                       const int* __restrict__ rowptr, int* cursor,
                       int* src, float* w, const float* __restrict__ dinv, int e) {
    int i = blockIdx.x * blockDim.x + threadIdx.x;
    if (i < e) {
        int r = row[i], c = col[i];
        int p = rowptr[c] + atomicAdd(&cursor[c], 1);
        src[p] = r;
        w[p] = dinv[r];
    }
}

// ---------------- aggregation over fp16 features: warp per node ----------------
// out[v] = act( dinv[v] * ( dinv[v]*h[v] + sum_e w[e]*h[src[e]] ) + bias )
template <int VEC, bool BIAS, bool RELU, bool OUTH>
__global__ void agg_h(const __half* __restrict__ h, void* __restrict__ outp,
                      const int* __restrict__ rowptr, const int* __restrict__ src,
                      const float* __restrict__ w, const float* __restrict__ dinv,
                      const float* __restrict__ bias, int nNodes) {
    constexpr int F = 32 * VEC;
    int gw = (blockIdx.x * blockDim.x + threadIdx.x) >> 5;
    int lane = threadIdx.x & 31;
    if (gw >= nNodes) return;
    int v = gw;
    int foff = lane * VEC;

    float acc[VEC];
    float dv = dinv[v];

    // self contribution
    {
        const __half* hp = h + (size_t)v * F + foff;
        if constexpr (VEC == 4) {
            uint2 r = *reinterpret_cast<const uint2*>(hp);
            float2 f0 = __half22float2(*reinterpret_cast<__half2*>(&r.x));
            float2 f1 = __half22float2(*reinterpret_cast<__half2*>(&r.y));
            acc[0] = dv * f0.x; acc[1] = dv * f0.y; acc[2] = dv * f1.x; acc[3] = dv * f1.y;
        } else if constexpr (VEC == 2) {
            float2 f = __half22float2(*reinterpret_cast<const __half2*>(hp));
            acc[0] = dv * f.x; acc[1] = dv * f.y;
        } else {
            acc[0] = dv * __half2float(*hp);
        }
    }

    int e0 = rowptr[v], e1 = rowptr[v + 1];
    int e = e0;
    for (; e + 4 <= e1; e += 4) {
        int s0 = src[e], s1 = src[e + 1], s2 = src[e + 2], s3 = src[e + 3];
        float w0 = w[e], w1 = w[e + 1], w2 = w[e + 2], w3 = w[e + 3];
        if constexpr (VEC == 4) {
            uint2 r0 = *reinterpret_cast<const uint2*>(h + (size_t)s0 * F + foff);
            uint2 r1 = *reinterpret_cast<const uint2*>(h + (size_t)s1 * F + foff);
            uint2 r2 = *reinterpret_cast<const uint2*>(h + (size_t)s2 * F + foff);
            uint2 r3 = *reinterpret_cast<const uint2*>(h + (size_t)s3 * F + foff);
            float2 a0 = __half22float2(*reinterpret_cast<__half2*>(&r0.x));
            float2 b0 = __half22float2(*reinterpret_cast<__half2*>(&r0.y));
            float2 a1 = __half22float2(*reinterpret_cast<__half2*>(&r1.x));
            float2 b1 = __half22float2(*reinterpret_cast<__half2*>(&r1.y));
            float2 a2 = __half22float2(*reinterpret_cast<__half2*>(&r2.x));
            float2 b2 = __half22float2(*reinterpret_cast<__half2*>(&r2.y));
            float2 a3 = __half22float2(*reinterpret_cast<__half2*>(&r3.x));
            float2 b3 = __half22float2(*reinterpret_cast<__half2*>(&r3.y));
            acc[0] += w0 * a0.x; acc[1] += w0 * a0.y; acc[2] += w0 * b0.x; acc[3] += w0 * b0.y;
            acc[0] += w1 * a1.x; acc[1] += w1 * a1.y; acc[2] += w1 * b1.x; acc[3] += w1 * b1.y;
            acc[0] += w2 * a2.x; acc[1] += w2 * a2.y; acc[2] += w2 * b2.x; acc[3] += w2 * b2.y;
            acc[0] += w3 * a3.x; acc[1] += w3 * a3.y; acc[2] += w3 * b3.x; acc[3] += w3 * b3.y;
        } else if constexpr (VEC == 2) {
            __half2 r0 = *reinterpret_cast<const __half2*>(h + (size_t)s0 * F + foff);
            __half2 r1 = *reinterpret_cast<const __half2*>(h + (size_t)s1 * F + foff);
            __half2 r2 = *reinterpret_cast<const __half2*>(h + (size_t)s2 * F + foff);
            __half2 r3 = *reinterpret_cast<const __half2*>(h + (size_t)s3 * F + foff);
            float2 f0 = __half22float2(r0), f1 = __half22float2(r1);
            float2 f2 = __half22float2(r2), f3 = __half22float2(r3);
            acc[0] += w0 * f0.x; acc[1] += w0 * f0.y;
            acc[0] += w1 * f1.x; acc[1] += w1 * f1.y;
            acc[0] += w2 * f2.x; acc[1] += w2 * f2.y;
            acc[0] += w3 * f3.x; acc[1] += w3 * f3.y;
        } else {
            float t0 = __half2float(h[(size_t)s0 * F + foff]);
            float t1 = __half2float(h[(size_t)s1 * F + foff]);
            float t2 = __half2float(h[(size_t)s2 * F + foff]);
            float t3 = __half2float(h[(size_t)s3 * F + foff]);
            acc[0] += w0 * t0 + w1 * t1 + w2 * t2 + w3 * t3;
        }
    }
    for (; e < e1; e++) {
        int s = src[e];
        float we = w[e];
        const __half* sp = h + (size_t)s * F + foff;
        if constexpr (VEC == 4) {
            uint2 r = *reinterpret_cast<const uint2*>(sp);
            float2 f0 = __half22float2(*reinterpret_cast<__half2*>(&r.x));
            float2 f1 = __half22float2(*reinterpret_cast<__half2*>(&r.y));
            acc[0] += we * f0.x; acc[1] += we * f0.y; acc[2] += we * f1.x; acc[3] += we * f1.y;
        } else if constexpr (VEC == 2) {
            float2 f = __half22float2(*reinterpret_cast<const __half2*>(sp));
            acc[0] += we * f.x; acc[1] += we * f.y;
        } else {
            acc[0] += we * __half2float(*sp);
        }
    }

    #pragma unroll
    for (int i = 0; i < VEC; i++) {
        float r = dv * acc[i];
        if (BIAS) r += bias[foff + i];
        if (RELU) r = fmaxf(r, 0.0f);
        acc[i] = r;
    }

    if constexpr (OUTH) {
        __half* op = (__half*)outp + (size_t)v * F + foff;
        #pragma unroll
        for (int i = 0; i < VEC; i++) op[i] = __float2half_rn(acc[i]);
    } else {
        float* op = (float*)outp + (size_t)v * F + foff;
        if constexpr (VEC == 4) {
            float4 t; t.x = acc[0]; t.y = acc[1]; t.z = acc[2]; t.w = acc[3];
            *reinterpret_cast<float4*>(op) = t;
        } else if constexpr (VEC == 2) {
            float2 t; t.x = acc[0]; t.y = acc[1];
            *reinterpret_cast<float2*>(op) = t;
        } else {
            op[0] = acc[0];
        }
    }
}

// ---------------- tf32 tensor-core GEMM (256 threads, 8 warps) ----------------
__device__ __forceinline__ uint32_t f2tf32(float f) {
    uint32_t o;
    asm("cvt.rna.tf32.f32 %0, %1;" : "=r"(o) : "f"(f));
    return o;
}

template <int AN, bool BIAS, bool RELU, bool OUTH>
__global__ __launch_bounds__(256, 2)
void gemm_tc(const float* __restrict__ A, const float* __restrict__ B,
             const float* __restrict__ bias, void* __restrict__ Cp,
             int M, int K, int Nc) {
    constexpr int BN = 2 * AN * 8;
    __shared__ uint32_t As[4][4][132][2];
    __shared__ uint32_t Bs[4][4][2][BN + 4];

    const int tid = threadIdx.x;
    const int lane = tid & 31, wid = tid >> 5;
    const int g = lane >> 2, tg = lane & 3;
    const int wm = wid & 3, wn = wid >> 2;

    const int bm = blockIdx.y * 128;
    const int bn = blockIdx.x * BN;

    float acc[2][AN][4];
    #pragma unroll
    for (int i = 0; i < 2; i++)
        #pragma unroll
        for (int j = 0; j < AN; j++)
            #pragma unroll
            for (int c = 0; c < 4; c++) acc[i][j][c] = 0.0f;

    const int arow_l = tid >> 1;
    const int khalf = (tid & 1) * 16;
    const int arow = min(bm + arow_l, M - 1);
    const float* Abase = A + (size_t)arow * K + khalf;

    const int bk = tid >> 3;
    const int bn_l = 4 * (tid & 7);

    for (int kt = 0; kt < K; kt += 32) {
        __syncthreads();
        #pragma unroll
        for (int q = 0; q < 4; q++) {
            float4 v = *reinterpret_cast<const float4*>(Abase + kt + q * 4);
            int kabs = khalf + q * 4;
            int kk = kabs >> 3, pr = (kabs >> 2) & 1;
            As[kk][0][arow_l][pr] = f2tf32(v.x);
            As[kk][1][arow_l][pr] = f2tf32(v.y);
            As[kk][2][arow_l][pr] = f2tf32(v.z);
            As[kk][3][arow_l][pr] = f2tf32(v.w);
        }
        {
            int kk = bk >> 3, pr = (bk >> 2) & 1, c4 = bk & 3;
            const float* Brow = B + (size_t)(kt + bk) * Nc + bn;
            uint32_t* dst = &Bs[kk][c4][pr][0];
            constexpr int NI = BN / 32;
            #pragma unroll
            for (int i = 0; i < NI; i++) {
                int n = bn_l + 32 * i;
                float4 v = *reinterpret_cast<const float4*>(Brow + n);
                uint4 o;
                o.x = f2tf32(v.x); o.y = f2tf32(v.y);
                o.z = f2tf32(v.z); o.w = f2tf32(v.w);
                *reinterpret_cast<uint4*>(dst + n) = o;
            }
        }
        __syncthreads();

        #pragma unroll
        for (int kk = 0; kk < 4; kk++) {
            uint32_t a[2][4];
            #pragma unroll
            for (int ma = 0; ma < 2; ma++) {
                int mb = wm * 32 + ma * 16;
                uint2 lo = *reinterpret_cast<const uint2*>(&As[kk][tg][mb + g][0]);
                uint2 hi = *reinterpret_cast<const uint2*>(&As[kk][tg][mb + 8 + g][0]);
                a[ma][0] = lo.x; a[ma][2] = lo.y;
                a[ma][1] = hi.x; a[ma][3] = hi.y;
            }
            uint32_t b[AN][2];
            #pragma unroll
            for (int na = 0; na < AN; na++) {
                int n = wn * AN * 8 + na * 8 + g;
                b[na][0] = Bs[kk][tg][0][n];
                b[na][1] = Bs[kk][tg][1][n];
            }
            #pragma unroll
            for (int ma = 0; ma < 2; ma++)
                #pragma unroll
                for (int na = 0; na < AN; na++) {
                    asm volatile(
                        "mma.sync.aligned.m16n8k8.row.col.f32.tf32.tf32.f32 "
                        "{%0,%1,%2,%3}, {%4,%5,%6,%7}, {%8,%9}, {%0,%1,%2,%3};\n"
                        : "+f"(acc[ma][na][0]), "+f"(acc[ma][na][1]),
                          "+f"(acc[ma][na][2]), "+f"(acc[ma][na][3])
                        : "r"(a[ma][0]), "r"(a[ma][1]), "r"(a[ma][2]), "r"(a[ma][3]),
                          "r"(b[na][0]), "r"(b[na][1]));
                }
        }
    }

    #pragma unroll
    for (int ma = 0; ma < 2; ma++) {
        int m0 = bm + wm * 32 + ma * 16 + g;
        #pragma unroll
        for (int na = 0; na < AN; na++) {
            int n = bn + wn * AN * 8 + na * 8 + 2 * tg;
            float bx = 0.f, by = 0.f;
            if (BIAS) { bx = bias[n]; by = bias[n + 1]; }
            float v0 = acc[ma][na][0] + bx, v1 = acc[ma][na][1] + by;
            float v2 = acc[ma][na][2] + bx, v3 = acc[ma][na][3] + by;
            if (RELU) {
                v0 = fmaxf(v0, 0.f); v1 = fmaxf(v1, 0.f);
                v2 = fmaxf(v2, 0.f); v3 = fmaxf(v3, 0.f);
            }
            if constexpr (OUTH) {
                __half* C = (__half*)Cp;
                if (m0 < M)
                    *reinterpret_cast<__half2*>(C + (size_t)m0 * Nc + n) = __floats2half2_rn(v0, v1);
                if (m0 + 8 < M)
                    *reinterpret_cast<__half2*>(C + (size_t)(m0 + 8) * Nc + n) = __floats2half2_rn(v2, v3);
            } else {
                float* C = (float*)Cp;
                if (m0 < M) {
                    float2 o; o.x = v0; o.y = v1;
                    *reinterpret_cast<float2*>(C + (size_t)m0 * Nc + n) = o;
                }
                if (m0 + 8 < M) {
                    float2 o; o.x = v2; o.y = v3;
                    *reinterpret_cast<float2*>(C + (size_t)(m0 + 8) * Nc + n) = o;
                }
            }
        }
    }
}

// ---------------- small fp32 GEMM (Nc <= 32) ----------------
template <int BN, int TN, bool BIAS, bool RELU, bool OUTH>
__global__ void gemm_k(const float* __restrict__ A, const float* __restrict__ B,
                       const float* __restrict__ bias, void* __restrict__ Cp,
                       int M, int K, int Nc) {
    constexpr int BM = 64, BK = 16, TM = 4;
    __shared__ float As[BK][BM];
    __shared__ float Bs[BK][BN];

    int tx = threadIdx.x & 15;
    int ty = threadIdx.x >> 4;
    int bm = blockIdx.y * BM;
    int bn = blockIdx.x * BN;

    float acc[TM][TN];
    #pragma unroll
    for (int i = 0; i < TM; i++)
        #pragma unroll
        for (int j = 0; j < TN; j++) acc[i][j] = 0.0f;

    for (int k0 = 0; k0 < K; k0 += BK) {
        #pragma unroll
        for (int i = 0; i < 4; i++) {
            int lin = threadIdx.x + i * 256;
            int m_l = lin >> 4;
            int k_l = lin & 15;
            int m = bm + m_l;
            As[k_l][m_l] = (m < M) ? A[(size_t)m * K + k0 + k_l] : 0.0f;
        }
        constexpr int BITER = (BK * BN) / 256;
        #pragma unroll
        for (int i = 0; i < BITER; i++) {
            int lin = threadIdx.x + i * 256;
            int k_l = lin / BN;
            int n_l = lin % BN;
            Bs[k_l][n_l] = B[(size_t)(k0 + k_l) * Nc + bn + n_l];
        }
        __syncthreads();

        #pragma unroll
        for (int k = 0; k < BK; k++) {
            float a[TM], b[TN];
            #pragma unroll
            for (int i = 0; i < TM; i++) a[i] = As[k][ty * TM + i];
            #pragma unroll
            for (int j = 0; j < TN; j++) b[j] = Bs[k][tx * TN + j];
            #pragma unroll
            for (int i = 0; i < TM; i++)
                #pragma unroll
                for (int j = 0; j < TN; j++) acc[i][j] += a[i] * b[j];
        }
        __syncthreads();
    }

    #pragma unroll
    for (int i = 0; i < TM; i++) {
        int m = bm + ty * TM + i;
        if (m < M) {
            #pragma unroll
            for (int j = 0; j < TN; j++) {
                int n = bn + tx * TN + j;
                float v = acc[i][j];
                if (BIAS) v += bias[n];
                if (RELU) v = fmaxf(v, 0.0f);
                if constexpr (OUTH)
                    ((__half*)Cp)[(size_t)m * Nc + n] = __float2half_rn(v);
                else
                    ((float*)Cp)[(size_t)m * Nc + n] = v;
            }
        }
    }
}

// ---------------- host ----------------
static inline void* sym(const void* s) {
    void* p = nullptr;
    cudaGetSymbolAddress(&p, s);
    return p;
}

extern "C" void kernel_launch(void* const* d_in, const int* in_sizes, int n_in,
                              void* d_out, int out_size) {
    const float* x   = (const float*)d_in[0];
    const int*   ei  = (const int*)d_in[1];
    const float* W1  = (const float*)d_in[2];
    const float* b1  = (const float*)d_in[3];
    const float* W2  = (const float*)d_in[4];
    const float* b2  = (const float*)d_in[5];
    const float* W3  = (const float*)d_in[6];
    const float* b3  = (const float*)d_in[7];
    const float* W4  = (const float*)d_in[8];
    const float* b4  = (const float*)d_in[9];
    const float* Wmu = (const float*)d_in[10];
    const float* bmu = (const float*)d_in[11];
    const float* Wls = (const float*)d_in[12];
    const float* bls = (const float*)d_in[13];

    const int N = NN;
    const int E = in_sizes[1] / 2;
    const int* row = ei;
    const int* col = ei + E;

    float* buf0 = (float*)sym(g_buf0);
    float* buf1 = (float*)sym(g_buf1);
    float* buf2 = (float*)sym(g_buf2);
    __half* hbuf2 = (__half*)buf2;   // x16 / t2 / t3 / t4
    __half* hbuf0 = (__half*)buf0;   // h4
    int*   deg  = (int*)sym(g_deg);
    int*   cur  = (int*)sym(g_cursor);
    int*   rp   = (int*)sym(g_rowptr);
    unsigned long long* desc = (unsigned long long*)sym(g_desc);
    int*   srcA = (int*)sym(g_src);
    float* wA   = (float*)sym(g_w);
    float* dinv = (float*)sym(g_dinv);

    float* out_mu = (float*)d_out;
    float* out_ls = out_mu + (size_t)N * 16;

    const int NB = (N + 255) / 256;
    const int n4 = N * 128 / 4;

    // ---- CSR build + x->fp16 (3 kernels + memsets) ----
    cudaMemsetAsync(deg, 0, NN * sizeof(int));
    cudaMemsetAsync(cur, 0, NN * sizeof(int));
    cudaMemsetAsync(desc, 0, 256 * sizeof(unsigned long long));
    histconv_k<<<(n4 + 255) / 256, 256>>>(col, deg, E, x, (__half2*)hbuf2, n4);
    scan_k<<<NB, 256>>>(deg, dinv, rp, desc, N, E);
    fill_k<<<(E + 255) / 256, 256>>>(row, col, rp, cur, srcA, wA, dinv, E);

    const int AGG_BLOCKS = (N + 7) / 8;  // 8 warps/block

    // ---- L1: agg(x16) F=128 -> fp32, tf32 GEMM +b1+relu -> h1 (N x 256 fp32) ----
    agg_h<4, false, false, false><<<AGG_BLOCKS, 256>>>(hbuf2, buf0, rp, srcA, wA, dinv, nullptr, N);
    {
        dim3 g(2, (N + 127) / 128);
        gemm_tc<8, true, true, false><<<g, 256>>>(buf0, W1, b1, buf1, N, 128, 256);
    }
    // ---- L2: transform (256->128) -> t2 half, agg +b2+relu -> fp32 ----
    {
        dim3 g(1, (N + 127) / 128);
        gemm_tc<8, false, false, true><<<g, 256>>>(buf1, W2, nullptr, hbuf2, N, 256, 128);
    }
    agg_h<4, true, true, false><<<AGG_BLOCKS, 256>>>(hbuf2, buf0, rp, srcA, wA, dinv, b2, N);
    // ---- L3: transform (128->64) -> t3 half, agg +b3+relu -> fp32 ----
    {
        dim3 g(1, (N + 127) / 128);
        gemm_tc<4, false, false, true><<<g, 256>>>(buf0, W3, nullptr, hbuf2, N, 128, 64);
    }
    agg_h<2, true, true, false><<<AGG_BLOCKS, 256>>>(hbuf2, buf1, rp, srcA, wA, dinv, b3, N);
    // ---- L4: transform (64->32) -> t4 half, agg +b4+relu -> h4 half ----
    {
        dim3 g(1, (N + 63) / 64);
        gemm_k<32, 2, false, false, true><<<g, 256>>>(buf1, W4, nullptr, hbuf2, N, 64, 32);
    }
    agg_h<1, true, true, true><<<AGG_BLOCKS, 256>>>(hbuf2, hbuf0, rp, srcA, wA, dinv, b4, N);
    // ---- heads: shared agg(h4) -> z fp32, two small fp32 GEMMs ----
    agg_h<1, false, false, false><<<AGG_BLOCKS, 256>>>(hbuf0, buf1, rp, srcA, wA, dinv, nullptr, N);
    {
        dim3 g(1, (N + 63) / 64);
        gemm_k<16, 1, true, false, false><<<g, 256>>>(buf1, Wmu, bmu, out_mu, N, 32, 16);
        gemm_k<16, 1, true, false, false><<<g, 256>>>(buf1, Wls, bls, out_ls, N, 32, 16);
    }
}

// round 7
// speedup vs baseline: 1.2761x; 1.2361x over previous
#include <cuda_runtime.h>
#include <cuda_fp16.h>
#include <cstddef>
#include <cstdint>

#define NN 50000
#define EE 800000

// ---------------- scratch ----------------
__device__ __half g_h0[NN * 256];    // ping
__device__ __half g_h1[NN * 256];    // pong
__device__ int   g_deg[NN];
__device__ int   g_cursor[NN];
__device__ int   g_rowptr[NN + 1];
__device__ unsigned long long g_desc[256];
__device__ int   g_src[EE];
__device__ float g_w[EE];            // w[p] = dinv[src[p]]
__device__ float g_dinv[NN];

// ---------------- CSR build + x->fp16 (fused) ----------------
__global__ void histconv_k(const int* __restrict__ col, int* deg, int e,
                           const float* __restrict__ x, __half2* __restrict__ x16,
                           int n4) {
    int i = blockIdx.x * blockDim.x + threadIdx.x;
    if (i < e) atomicAdd(&deg[col[i]], 1);
    if (i < n4) {
        float4 v = reinterpret_cast<const float4*>(x)[i];
        x16[2 * i]     = __floats2half2_rn(v.x, v.y);
        x16[2 * i + 1] = __floats2half2_rn(v.z, v.w);
    }
}

// fused: dinv + single-pass exclusive scan of deg via decoupled lookback
__global__ void scan_k(const int* __restrict__ deg, float* __restrict__ dinv,
                       int* __restrict__ rowptr, unsigned long long* desc,
                       int n, int total) {
    int b = blockIdx.x;
    int i = b * 256 + threadIdx.x;
    int lane = threadIdx.x & 31, wid = threadIdx.x >> 5;

    int v = (i < n) ? deg[i] : 0;
    if (i < n) dinv[i] = rsqrtf((float)(v + 1));

    int x = v;
    #pragma unroll
    for (int off = 1; off < 32; off <<= 1) {
        int t = __shfl_up_sync(0xFFFFFFFFu, x, off);
        if (lane >= off) x += t;
    }
    __shared__ int ws[8];
    __shared__ int s_prefix;
    if (lane == 31) ws[wid] = x;
    __syncthreads();
    if (wid == 0 && lane < 8) {
        int w = ws[lane];
        #pragma unroll
        for (int off = 1; off < 8; off <<= 1) {
            int t = __shfl_up_sync(0xFFu, w, off);
            if (lane >= off) w += t;
        }
        ws[lane] = w;
    }
    __syncthreads();
    int agg = ws[7];

    if (threadIdx.x == 0) {
        if (b == 0) {
            atomicExch(&desc[0], (2ull << 32) | (unsigned)agg);
            s_prefix = 0;
            rowptr[n] = total;
        } else {
            __threadfence();
            atomicExch(&desc[b], (1ull << 32) | (unsigned)agg);
            int prefix = 0;
            int j = b - 1;
            while (true) {
                unsigned long long dj;
                do { dj = atomicAdd(&desc[j], 0ull); } while ((dj >> 32) == 0);
                prefix += (int)(unsigned)dj;
                if ((dj >> 32) == 2) break;
                j--;
            }
            __threadfence();
            atomicExch(&desc[b], (2ull << 32) | (unsigned)(prefix + agg));
            s_prefix = prefix;
        }
    }
    __syncthreads();
    int excl = s_prefix + (wid ? ws[wid - 1] : 0) + (x - v);
    if (i < n) rowptr[i] = excl;
}

__global__ void fill_k(const int* __restrict__ row, const int* __restrict__ col,
                       const int* __restrict__ rowptr, int* cursor,
                       int* src, float* w, const float* __restrict__ dinv, int e) {
    int i = blockIdx.x * blockDim.x + threadIdx.x;
    if (i < e) {
        int r = row[i], c = col[i];
        int p = rowptr[c] + atomicAdd(&cursor[c], 1);
        src[p] = r;
        w[p] = dinv[r];
    }
}

// ---------------- aggregation (fp16 in, fp16 out), warp per node ----------------
template <int VEC, bool BIAS, bool RELU>
__global__ void agg_h(const __half* __restrict__ h, __half* __restrict__ out,
                      const int* __restrict__ rowptr, const int* __restrict__ src,
                      const float* __restrict__ w, const float* __restrict__ dinv,
                      const float* __restrict__ bias, int nNodes) {
    constexpr int F = 32 * VEC;
    int gw = (blockIdx.x * blockDim.x + threadIdx.x) >> 5;
    int lane = threadIdx.x & 31;
    if (gw >= nNodes) return;
    int v = gw;
    int foff = lane * VEC;

    float acc[VEC];
    float dv = dinv[v];

    {
        const __half* hp = h + (size_t)v * F + foff;
        if constexpr (VEC == 4) {
            uint2 r = *reinterpret_cast<const uint2*>(hp);
            float2 f0 = __half22float2(*reinterpret_cast<__half2*>(&r.x));
            float2 f1 = __half22float2(*reinterpret_cast<__half2*>(&r.y));
            acc[0] = dv * f0.x; acc[1] = dv * f0.y; acc[2] = dv * f1.x; acc[3] = dv * f1.y;
        } else if constexpr (VEC == 2) {
            float2 f = __half22float2(*reinterpret_cast<const __half2*>(hp));
            acc[0] = dv * f.x; acc[1] = dv * f.y;
        } else {
            acc[0] = dv * __half2float(*hp);
        }
    }

    int e0 = rowptr[v], e1 = rowptr[v + 1];
    int e = e0;
    for (; e + 4 <= e1; e += 4) {
        int s0 = src[e], s1 = src[e + 1], s2 = src[e + 2], s3 = src[e + 3];
        float w0 = w[e], w1 = w[e + 1], w2 = w[e + 2], w3 = w[e + 3];
        if constexpr (VEC == 4) {
            uint2 r0 = *reinterpret_cast<const uint2*>(h + (size_t)s0 * F + foff);
            uint2 r1 = *reinterpret_cast<const uint2*>(h + (size_t)s1 * F + foff);
            uint2 r2 = *reinterpret_cast<const uint2*>(h + (size_t)s2 * F + foff);
            uint2 r3 = *reinterpret_cast<const uint2*>(h + (size_t)s3 * F + foff);
            float2 a0 = __half22float2(*reinterpret_cast<__half2*>(&r0.x));
            float2 b0 = __half22float2(*reinterpret_cast<__half2*>(&r0.y));
            float2 a1 = __half22float2(*reinterpret_cast<__half2*>(&r1.x));
            float2 b1 = __half22float2(*reinterpret_cast<__half2*>(&r1.y));
            float2 a2 = __half22float2(*reinterpret_cast<__half2*>(&r2.x));
            float2 b2 = __half22float2(*reinterpret_cast<__half2*>(&r2.y));
            float2 a3 = __half22float2(*reinterpret_cast<__half2*>(&r3.x));
            float2 b3 = __half22float2(*reinterpret_cast<__half2*>(&r3.y));
            acc[0] += w0 * a0.x; acc[1] += w0 * a0.y; acc[2] += w0 * b0.x; acc[3] += w0 * b0.y;
            acc[0] += w1 * a1.x; acc[1] += w1 * a1.y; acc[2] += w1 * b1.x; acc[3] += w1 * b1.y;
            acc[0] += w2 * a2.x; acc[1] += w2 * a2.y; acc[2] += w2 * b2.x; acc[3] += w2 * b2.y;
            acc[0] += w3 * a3.x; acc[1] += w3 * a3.y; acc[2] += w3 * b3.x; acc[3] += w3 * b3.y;
        } else if constexpr (VEC == 2) {
            __half2 r0 = *reinterpret_cast<const __half2*>(h + (size_t)s0 * F + foff);
            __half2 r1 = *reinterpret_cast<const __half2*>(h + (size_t)s1 * F + foff);
            __half2 r2 = *reinterpret_cast<const __half2*>(h + (size_t)s2 * F + foff);
            __half2 r3 = *reinterpret_cast<const __half2*>(h + (size_t)s3 * F + foff);
            float2 f0 = __half22float2(r0), f1 = __half22float2(r1);
            float2 f2 = __half22float2(r2), f3 = __half22float2(r3);
            acc[0] += w0 * f0.x; acc[1] += w0 * f0.y;
            acc[0] += w1 * f1.x; acc[1] += w1 * f1.y;
            acc[0] += w2 * f2.x; acc[1] += w2 * f2.y;
            acc[0] += w3 * f3.x; acc[1] += w3 * f3.y;
        } else {
            float t0 = __half2float(h[(size_t)s0 * F + foff]);
            float t1 = __half2float(h[(size_t)s1 * F + foff]);
            float t2 = __half2float(h[(size_t)s2 * F + foff]);
            float t3 = __half2float(h[(size_t)s3 * F + foff]);
            acc[0] += w0 * t0 + w1 * t1 + w2 * t2 + w3 * t3;
        }
    }
    for (; e < e1; e++) {
        int s = src[e];
        float we = w[e];
        const __half* sp = h + (size_t)s * F + foff;
        if constexpr (VEC == 4) {
            uint2 r = *reinterpret_cast<const uint2*>(sp);
            float2 f0 = __half22float2(*reinterpret_cast<__half2*>(&r.x));
            float2 f1 = __half22float2(*reinterpret_cast<__half2*>(&r.y));
            acc[0] += we * f0.x; acc[1] += we * f0.y; acc[2] += we * f1.x; acc[3] += we * f1.y;
        } else if constexpr (VEC == 2) {
            float2 f = __half22float2(*reinterpret_cast<const __half2*>(sp));
            acc[0] += we * f.x; acc[1] += we * f.y;
        } else {
            acc[0] += we * __half2float(*sp);
        }
    }

    #pragma unroll
    for (int i = 0; i < VEC; i++) {
        float r = dv * acc[i];
        if (BIAS) r += bias[foff + i];
        if (RELU) r = fmaxf(r, 0.0f);
        acc[i] = r;
    }

    __half* op = out + (size_t)v * F + foff;
    if constexpr (VEC == 4) {
        uint2 o;
        *reinterpret_cast<__half2*>(&o.x) = __floats2half2_rn(acc[0], acc[1]);
        *reinterpret_cast<__half2*>(&o.y) = __floats2half2_rn(acc[2], acc[3]);
        *reinterpret_cast<uint2*>(op) = o;
    } else if constexpr (VEC == 2) {
        *reinterpret_cast<__half2*>(op) = __floats2half2_rn(acc[0], acc[1]);
    } else {
        op[0] = __float2half_rn(acc[0]);
    }
}

// ---------------- fp16 tensor-core GEMM (m16n8k16, 256 threads, 8 warps) ----------------
// C[M,Nc] = A[M,K](half) @ B[K,Nc](fp32->half) (+bias)(+relu). Block 128m x BN,
// BN = 2*AN*8. Warp layout 4m x 2n; warp tile 32m x (AN*8). K multiple of 32.
template <int AN, bool BIAS, bool RELU, bool OUTH>
__global__ __launch_bounds__(256, 2)
void gemm_h(const __half* __restrict__ A, const float* __restrict__ B,
            const float* __restrict__ bias, void* __restrict__ Cp,
            int M, int K, int Nc) {
    constexpr int BN = 2 * AN * 8;
    // k = kk*16 + p*8 + c*2 (+0/1 inside the uint32 pair)
    __shared__ uint32_t As[2][4][132][2];        // [kk][c][m][p]
    __shared__ uint32_t Bs[2][4][2][BN + 4];     // [kk][c][p][n]

    const int tid = threadIdx.x;
    const int lane = tid & 31, wid = tid >> 5;
    const int g = lane >> 2, tg = lane & 3;
    const int wm = wid & 3, wn = wid >> 2;

    const int bm = blockIdx.y * 128;
    const int bn = blockIdx.x * BN;

    float acc[2][AN][4];
    #pragma unroll
    for (int i = 0; i < 2; i++)
        #pragma unroll
        for (int j = 0; j < AN; j++)
            #pragma unroll
            for (int c = 0; c < 4; c++) acc[i][j][c] = 0.0f;

    const int arow_l = tid >> 1;            // 0..127
    const int kh = (tid & 1) * 16;          // 0 / 16
    const int akk = kh >> 4;
    const int arow = min(bm + arow_l, M - 1);
    const __half* Abase = A + (size_t)arow * K + kh;

    const int kp = tid >> 4;                // 0..15 : B k-row pair (2kp, 2kp+1)
    const int kloc = kp * 2;
    const int bkk = kloc >> 4, bp = (kloc >> 3) & 1, bc = (kloc >> 1) & 3;
    const int nseg = tid & 15;

    for (int kt = 0; kt < K; kt += 32) {
        __syncthreads();
        // ---- fill A: 16 halves (two uint4) per thread; uint32s are ready k-pairs ----
        {
            uint4 v0 = *reinterpret_cast<const uint4*>(Abase + kt);      // k = kh .. kh+7
            uint4 v1 = *reinterpret_cast<const uint4*>(Abase + kt + 8);  // k = kh+8 .. kh+15
            As[akk][0][arow_l][0] = v0.x;
            As[akk][1][arow_l][0] = v0.y;
            As[akk][2][arow_l][0] = v0.z;
            As[akk][3][arow_l][0] = v0.w;
            As[akk][0][arow_l][1] = v1.x;
            As[akk][1][arow_l][1] = v1.y;
            As[akk][2][arow_l][1] = v1.z;
            As[akk][3][arow_l][1] = v1.w;
        }
        // ---- fill B: rows (kt+kloc, kt+kloc+1), cols nseg + 16*j ----
        {
            const float* r0 = B + (size_t)(kt + kloc) * Nc + bn;
            const float* r1 = r0 + Nc;
            #pragma unroll
            for (int j = 0; j < BN / 16; j++) {
                int n = nseg + 16 * j;
                __half2 pk = __floats2half2_rn(r0[n], r1[n]);  // low = even k
                Bs[bkk][bc][bp][n] = *reinterpret_cast<uint32_t*>(&pk);
            }
        }
        __syncthreads();

        // ---- 2 k16 mma steps ----
        #pragma unroll
        for (int kk = 0; kk < 2; kk++) {
            uint32_t a[2][4];
            #pragma unroll
            for (int ma = 0; ma < 2; ma++) {
                int mb = wm * 32 + ma * 16;
                uint2 lo = *reinterpret_cast<const uint2*>(&As[kk][tg][mb + g][0]);
                uint2 hi = *reinterpret_cast<const uint2*>(&As[kk][tg][mb + 8 + g][0]);
                a[ma][0] = lo.x; a[ma][2] = lo.y;   // row g:   k-lo, k-hi
                a[ma][1] = hi.x; a[ma][3] = hi.y;   // row g+8
            }
            uint32_t b[AN][2];
            #pragma unroll
            for (int na = 0; na < AN; na++) {
                int n = wn * AN * 8 + na * 8 + g;
                b[na][0] = Bs[kk][tg][0][n];
                b[na][1] = Bs[kk][tg][1][n];
            }
            #pragma unroll
            for (int ma = 0; ma < 2; ma++)
                #pragma unroll
                for (int na = 0; na < AN; na++) {
                    asm volatile(
                        "mma.sync.aligned.m16n8k16.row.col.f32.f16.f16.f32 "
                        "{%0,%1,%2,%3}, {%4,%5,%6,%7}, {%8,%9}, {%0,%1,%2,%3};\n"
                        : "+f"(acc[ma][na][0]), "+f"(acc[ma][na][1]),
                          "+f"(acc[ma][na][2]), "+f"(acc[ma][na][3])
                        : "r"(a[ma][0]), "r"(a[ma][1]), "r"(a[ma][2]), "r"(a[ma][3]),
                          "r"(b[na][0]), "r"(b[na][1]));
                }
        }
    }

    // ---- epilogue ----
    #pragma unroll
    for (int ma = 0; ma < 2; ma++) {
        int m0 = bm + wm * 32 + ma * 16 + g;
        #pragma unroll
        for (int na = 0; na < AN; na++) {
            int n = bn + wn * AN * 8 + na * 8 + 2 * tg;
            float bx = 0.f, by = 0.f;
            if (BIAS) { bx = bias[n]; by = bias[n + 1]; }
            float v0 = acc[ma][na][0] + bx, v1 = acc[ma][na][1] + by;
            float v2 = acc[ma][na][2] + bx, v3 = acc[ma][na][3] + by;
            if (RELU) {
                v0 = fmaxf(v0, 0.f); v1 = fmaxf(v1, 0.f);
                v2 = fmaxf(v2, 0.f); v3 = fmaxf(v3, 0.f);
            }
            if constexpr (OUTH) {
                __half* C = (__half*)Cp;
                if (m0 < M)
                    *reinterpret_cast<__half2*>(C + (size_t)m0 * Nc + n) = __floats2half2_rn(v0, v1);
                if (m0 + 8 < M)
                    *reinterpret_cast<__half2*>(C + (size_t)(m0 + 8) * Nc + n) = __floats2half2_rn(v2, v3);
            } else {
                float* C = (float*)Cp;
                if (m0 < M) {
                    float2 o; o.x = v0; o.y = v1;
                    *reinterpret_cast<float2*>(C + (size_t)m0 * Nc + n) = o;
                }
                if (m0 + 8 < M) {
                    float2 o; o.x = v2; o.y = v3;
                    *reinterpret_cast<float2*>(C + (size_t)(m0 + 8) * Nc + n) = o;
                }
            }
        }
    }
}

// ---------------- fused heads: mu = zWmu+bmu, ls = zWls+bls (thread per node) ----------------
__global__ __launch_bounds__(256)
void heads_k(const __half* __restrict__ z, const float* __restrict__ Wmu,
             const float* __restrict__ bmu, const float* __restrict__ Wls,
             const float* __restrict__ bls, float* __restrict__ out_mu,
             float* __restrict__ out_ls, int n) {
    __shared__ float sWmu[32][16];
    __shared__ float sWls[32][16];
    __shared__ float sb[32];
    {
        int t = threadIdx.x;
        if (t < 256) {
            // 32*16 = 512 floats each; 256 threads -> 2 each
            sWmu[t >> 4][t & 15] = Wmu[t];
            sWmu[(t + 256) >> 4][t & 15] = Wmu[t + 256];
            sWls[t >> 4][t & 15] = Wls[t];
            sWls[(t + 256) >> 4][t & 15] = Wls[t + 256];
            if (t < 16) sb[t] = bmu[t];
            else if (t < 32) sb[t] = bls[t - 16];
        }
    }
    __syncthreads();

    int v = blockIdx.x * 256 + threadIdx.x;
    if (v >= n) return;

    // load 32 halves of z
    float zf[32];
    {
        const uint4* zp = reinterpret_cast<const uint4*>(z + (size_t)v * 32);
        #pragma unroll
        for (int q = 0; q < 4; q++) {
            uint4 r = zp[q];
            uint32_t u[4] = {r.x, r.y, r.z, r.w};
            #pragma unroll
            for (int j = 0; j < 4; j++) {
                float2 f = __half22float2(*reinterpret_cast<__half2*>(&u[j]));
                zf[q * 8 + j * 2] = f.x;
                zf[q * 8 + j * 2 + 1] = f.y;
            }
        }
    }

    float amu[16], als[16];
    #pragma unroll
    for (int i = 0; i < 16; i++) { amu[i] = sb[i]; als[i] = sb[16 + i]; }
    #pragma unroll
    for (int k = 0; k < 32; k++) {
        float zk = zf[k];
        #pragma unroll
        for (int i = 0; i < 16; i++) {
            amu[i] += zk * sWmu[k][i];
            als[i] += zk * sWls[k][i];
        }
    }

    float4* om = reinterpret_cast<float4*>(out_mu + (size_t)v * 16);
    float4* ol = reinterpret_cast<float4*>(out_ls + (size_t)v * 16);
    #pragma unroll
    for (int q = 0; q < 4; q++) {
        om[q] = make_float4(amu[q * 4], amu[q * 4 + 1], amu[q * 4 + 2], amu[q * 4 + 3]);
        ol[q] = make_float4(als[q * 4], als[q * 4 + 1], als[q * 4 + 2], als[q * 4 + 3]);
    }
}

// ---------------- host ----------------
static inline void* sym(const void* s) {
    void* p = nullptr;
    cudaGetSymbolAddress(&p, s);
    return p;
}

extern "C" void kernel_launch(void* const* d_in, const int* in_sizes, int n_in,
                              void* d_out, int out_size) {
    const float* x   = (const float*)d_in[0];
    const int*   ei  = (const int*)d_in[1];
    const float* W1  = (const float*)d_in[2];
    const float* b1  = (const float*)d_in[3];
    const float* W2  = (const float*)d_in[4];
    const float* b2  = (const float*)d_in[5];
    const float* W3  = (const float*)d_in[6];
    const float* b3  = (const float*)d_in[7];
    const float* W4  = (const float*)d_in[8];
    const float* b4  = (const float*)d_in[9];
    const float* Wmu = (const float*)d_in[10];
    const float* bmu = (const float*)d_in[11];
    const float* Wls = (const float*)d_in[12];
    const float* bls = (const float*)d_in[13];

    const int N = NN;
    const int E = in_sizes[1] / 2;
    const int* row = ei;
    const int* col = ei + E;

    __half* h0 = (__half*)sym(g_h0);
    __half* h1 = (__half*)sym(g_h1);
    int*   deg  = (int*)sym(g_deg);
    int*   cur  = (int*)sym(g_cursor);
    int*   rp   = (int*)sym(g_rowptr);
    unsigned long long* desc = (unsigned long long*)sym(g_desc);
    int*   srcA = (int*)sym(g_src);
    float* wA   = (float*)sym(g_w);
    float* dinv = (float*)sym(g_dinv);

    float* out_mu = (float*)d_out;
    float* out_ls = out_mu + (size_t)N * 16;

    const int NB = (N + 255) / 256;
    const int n4 = N * 128 / 4;

    // ---- CSR build + x->fp16 ----
    cudaMemsetAsync(deg, 0, NN * sizeof(int));
    cudaMemsetAsync(cur, 0, NN * sizeof(int));
    cudaMemsetAsync(desc, 0, 256 * sizeof(unsigned long long));
    histconv_k<<<(n4 + 255) / 256, 256>>>(col, deg, E, x, (__half2*)h0, n4);   // x16 -> h0
    scan_k<<<NB, 256>>>(deg, dinv, rp, desc, N, E);
    fill_k<<<(E + 255) / 256, 256>>>(row, col, rp, cur, srcA, wA, dinv, E);

    const int AGG_BLOCKS = (N + 7) / 8;
    const int GY = (N + 127) / 128;

    // L1: agg(x16:h0) -> a1:h1 ; gemm(a1, W1) +b1+relu -> h1g:h0 [N,256]
    agg_h<4, false, false><<<AGG_BLOCKS, 256>>>(h0, h1, rp, srcA, wA, dinv, nullptr, N);
    { dim3 g(2, GY); gemm_h<8, true, true, true><<<g, 256>>>(h1, W1, b1, h0, N, 128, 256); }
    // L2: gemm(h1g, W2) -> t2:h1 [N,128] ; agg +b2+relu -> a2:h0
    { dim3 g(1, GY); gemm_h<8, false, false, true><<<g, 256>>>(h0, W2, nullptr, h1, N, 256, 128); }
    agg_h<4, true, true><<<AGG_BLOCKS, 256>>>(h1, h0, rp, srcA, wA, dinv, b2, N);
    // L3: gemm(a2, W3) -> t3:h1 [N,64] ; agg +b3+relu -> a3:h0
    { dim3 g(1, GY); gemm_h<4, false, false, true><<<g, 256>>>(h0, W3, nullptr, h1, N, 128, 64); }
    agg_h<2, true, true><<<AGG_BLOCKS, 256>>>(h1, h0, rp, srcA, wA, dinv, b3, N);
    // L4: gemm(a3, W4) -> t4:h1 [N,32] ; agg +b4+relu -> h4:h0
    { dim3 g(1, GY); gemm_h<2, false, false, true><<<g, 256>>>(h0, W4, nullptr, h1, N, 64, 32); }
    agg_h<1, true, true><<<AGG_BLOCKS, 256>>>(h1, h0, rp, srcA, wA, dinv, b4, N);
    // heads: agg(h4) -> z:h1 ; fused mu/ls GEMM
    agg_h<1, false, false><<<AGG_BLOCKS, 256>>>(h0, h1, rp, srcA, wA, dinv, nullptr, N);
    heads_k<<<NB, 256>>>(h1, Wmu, bmu, Wls, bls, out_mu, out_ls, N);
}